// round 12
// baseline (speedup 1.0000x reference)
#include <cuda_runtime.h>
#include <cuda_bf16.h>
#include <math.h>

// Global accumulators (zero at module load; last block resets each run).
__device__ float        g_bins[128];
__device__ int          g_cnt[128];
__device__ float        g_cls_sum;
__device__ float        g_box_sum;
__device__ unsigned int g_arrive;

#define TILE_CAP 6724   // 82*82 floats = 26.9KB: max bilinear support region

// ---------------------------------------------------------------------------
// Single fused kernel: one block (256 thr) per RoI r.
//   phase A (all 8 warps): cooperatively stage the RoI's gt_mask support
//     region (coalesced LDG -> STS) into smem tile.
//   phase B: warps 0-6 compute mask BCE from the tile via LDS (29cyc instead
//     of ~250cyc L2 gathers); warp 7 does cls CE + box smooth-L1.
//   epilogue (identical to the 14.8us best): block reduce, tid0 atomics +
//     single release-arrive; last block finalizes via __ldcg and resets.
// ---------------------------------------------------------------------------
template<int MO>
__global__ void __launch_bounds__(256, 5) fused_kernel(
        const float* __restrict__ class_logit,
        const float* __restrict__ box_regression,
        const float* __restrict__ regression_target,
        const float* __restrict__ mask_logit,
        const float* __restrict__ proposal,
        const float* __restrict__ gt_mask,
        const int* __restrict__ matched_idx,
        const int* __restrict__ label,
        float* __restrict__ out,
        int C, int Hh, int Ww, int Mo_rt, int num_pos, int R, int G) {
    const int Mo = (MO > 0) ? MO : Mo_rt;
    const int P  = Mo * Mo;
    int r    = blockIdx.x;
    int tid  = threadIdx.x;
    int lane = tid & 31;
    int w    = tid >> 5;
    __shared__ float tile[TILE_CAP];
    __shared__ float sh[8];
    __shared__ bool  s_last;

    int lab = __ldg(&label[r]);
    int b   = __ldg(&matched_idx[r]);

    // ---- box geometry (uniform per block; every thread computes) ----
    float4 box = *(const float4*)(proposal + (size_t)r * 4);
    float x1 = box.x, y1 = box.y, x2 = box.z, y2 = box.w;
    float invMo = 1.0f / (float)Mo;
    float sx = (x2 - x1) * invMo;
    float sy = (y2 - y1) * invMo;
    const float* fm = gt_mask + (size_t)b * Hh * Ww;

    // support region of all clamped sample coords (sx,sy > 0 by construction)
    float xc_lo = fminf(fmaxf(fmaf(0.5f, sx, x1), 0.0f), (float)(Ww - 1));
    float xc_hi = fminf(fmaxf(fmaf((float)Mo - 0.5f, sx, x1), 0.0f), (float)(Ww - 1));
    float yc_lo = fminf(fmaxf(fmaf(0.5f, sy, y1), 0.0f), (float)(Hh - 1));
    float yc_hi = fminf(fmaxf(fmaf((float)Mo - 0.5f, sy, y1), 0.0f), (float)(Hh - 1));
    int x_lo = (int)xc_lo;
    int x_hi = min((int)xc_hi + 1, Ww - 1);
    int y_lo = (int)yc_lo;
    int y_hi = min((int)yc_hi + 1, Hh - 1);
    int width  = x_hi - x_lo + 1;
    int height = y_hi - y_lo + 1;
    bool use_tile = (MO == 28) && (width * height <= TILE_CAP);

    // ---- phase A: cooperative coalesced staging (all 8 warps) ----
    if (use_tile) {
        const float* src = fm + (size_t)y_lo * Ww + x_lo;
        for (int row = w; row < height; row += 8) {
            const float* srow = src + (size_t)row * Ww;
            float* drow = tile + row * width;
            for (int col = lane; col < width; col += 32)
                drow[col] = __ldg(srow + col);
        }
    }
    __syncthreads();

    if (w == 7) {
        // ---- classification CE for this row ----
        const float* row = class_logit + (size_t)r * C;
        float e0 = (lane      < C) ? __ldg(row + lane)      : -INFINITY;
        float e1 = (lane + 32 < C) ? __ldg(row + lane + 32) : -INFINITY;
        float e2 = (lane + 64 < C) ? __ldg(row + lane + 64) : -INFINITY;
        float mx = fmaxf(e0, fmaxf(e1, e2));
        #pragma unroll
        for (int o = 16; o; o >>= 1) mx = fmaxf(mx, __shfl_xor_sync(0xFFFFFFFFu, mx, o));
        float s2 = 0.0f;
        if (lane      < C) s2 += __expf(e0 - mx);
        if (lane + 32 < C) s2 += __expf(e1 - mx);
        if (lane + 64 < C) s2 += __expf(e2 - mx);
        #pragma unroll
        for (int o = 16; o; o >>= 1) s2 += __shfl_xor_sync(0xFFFFFFFFu, s2, o);
        if (lane == 0) atomicAdd(&g_cls_sum, mx + __logf(s2) - __ldg(row + lab));

        // ---- box smooth-L1 for this row (if positive) ----
        if (r < num_pos) {
            float term = 0.0f;
            if (lane < 4) {
                float pred = __ldg(&box_regression[(size_t)r * (C * 4) + lab * 4 + lane]);
                float tgt  = __ldg(&regression_target[r * 4 + lane]);
                float d = fabsf(pred - tgt);
                term = (d < 1.0f) ? 0.5f * d * d : d - 0.5f;
            }
            #pragma unroll
            for (int o = 2; o; o >>= 1) term += __shfl_xor_sync(0xFFFFFFFFu, term, o);
            if (lane == 0) atomicAdd(&g_box_sum, term);
        }
        if (lane == 0) sh[7] = 0.0f;
    } else {
        // ---- mask BCE (phase B) ----
        float acc  = 0.0f;
        float prod = 1.0f;
        const float* sel = mask_logit + ((size_t)r * C + lab) * P;

        if (MO == 28 && use_tile) {
            const int ix = lane;                 // lanes 0..27 active
            const bool active = ix < 28;

            float x  = fmaf((float)ix + 0.5f, sx, x1);
            bool  vx = (x > -1.0f) & (x < (float)Ww);
            float xc = fminf(fmaxf(x, 0.0f), (float)(Ww - 1));
            int   x0 = (int)xc;
            int   xi = min(x0 + 1, Ww - 1);
            float lx = xc - (float)x0;
            int c0 = x0 - x_lo;
            int c1 = xi - x_lo;

            #pragma unroll
            for (int i = 0; i < 4; i++) {
                int row = (w << 2) + i;
                float y = fmaf((float)row + 0.5f, sy, y1);
                bool valid = active & vx & (y > -1.0f) & (y < (float)Hh);
                float yc = fminf(fmaxf(y, 0.0f), (float)(Hh - 1));
                int y0 = (int)yc;
                int yi = min(y0 + 1, Hh - 1);
                float ly = yc - (float)y0;
                const float* t0 = tile + (y0 - y_lo) * width;
                const float* t1 = tile + (yi - y_lo) * width;
                float v00 = t0[c0];
                float v01 = t0[c1];
                float v10 = t1[c0];
                float v11 = t1[c1];
                float s   = active ? __ldg(sel + row * 28 + ix) : 0.0f;
                float top = fmaf(lx, v01 - v00, v00);
                float bot = fmaf(lx, v11 - v10, v10);
                float t = fmaf(ly, bot - top, top);
                t = valid ? t : 0.0f;
                acc += fmaxf(s, 0.0f) - s * t;
                float f = 1.0f + __expf(-fabsf(s));
                prod *= active ? f : 1.0f;
            }
        } else {
            // fallback: direct gathers (generic Mo, or oversized region)
            for (int p = tid; p < P; p += 224) {
                int iy = p / Mo;
                int ix = p - iy * Mo;
                float x = fmaf((float)ix + 0.5f, sx, x1);
                float y = fmaf((float)iy + 0.5f, sy, y1);
                bool valid = (x > -1.0f) & (x < (float)Ww) & (y > -1.0f) & (y < (float)Hh);
                float xc = fminf(fmaxf(x, 0.0f), (float)(Ww - 1));
                float yc = fminf(fmaxf(y, 0.0f), (float)(Hh - 1));
                int x0 = (int)xc, y0 = (int)yc;
                int xi = min(x0 + 1, Ww - 1);
                int yi = min(y0 + 1, Hh - 1);
                float lx = xc - (float)x0, ly = yc - (float)y0;
                const float* r0 = fm + (size_t)y0 * Ww;
                const float* r1 = fm + (size_t)yi * Ww;
                float v00 = __ldg(r0 + x0), v01 = __ldg(r0 + xi);
                float v10 = __ldg(r1 + x0), v11 = __ldg(r1 + xi);
                float top = fmaf(lx, v01 - v00, v00);
                float bot = fmaf(lx, v11 - v10, v10);
                float t = fmaf(ly, bot - top, top);
                t = valid ? t : 0.0f;
                float s = __ldg(sel + p);
                acc  += fmaxf(s, 0.0f) - s * t;
                prod *= 1.0f + __expf(-fabsf(s));
            }
        }

        // product across 8-lane groups (factors in (1,2])
        #pragma unroll
        for (int o = 1; o < 8; o <<= 1) prod *= __shfl_xor_sync(0xFFFFFFFFu, prod, o);
        if ((lane & 7) == 0) acc += __logf(prod);

        #pragma unroll
        for (int o = 16; o; o >>= 1) acc += __shfl_xor_sync(0xFFFFFFFFu, acc, o);
        if (lane == 0) sh[w] = acc;
    }
    __syncthreads();

    if (w == 0) {
        float v = (lane < 8) ? sh[lane] : 0.0f;
        #pragma unroll
        for (int o = 4; o; o >>= 1) v += __shfl_xor_sync(0xFFFFFFFFu, v, o);
        if (lane == 0) {
            atomicAdd(&g_bins[b], v / (float)P);
            atomicAdd(&g_cnt[b], 1);
        }
    }
    __syncthreads();

    // ---- last-block finalize: RELEASE-only arrive (no L1 invalidate) ----
    if (tid == 0) {
        unsigned int n;
        asm volatile("atom.release.gpu.global.add.u32 %0, [%1], 1;"
                     : "=r"(n) : "l"(&g_arrive) : "memory");
        s_last = (n == (unsigned int)(gridDim.x - 1));
    }
    __syncthreads();
    if (s_last) {
        if (tid == 0) out[0] = __ldcg(&g_cls_sum) / (float)R;
        if (tid == 1) out[1] = __ldcg(&g_box_sum) / (float)R;
        if (tid < G) {
            int c = __ldcg(&g_cnt[tid]);
            float bsum = __ldcg(&g_bins[tid]);
            out[2 + tid] = (c > 0) ? bsum / (float)c : 0.0f;
        }
        __syncthreads();
        if (tid == 0) { g_cls_sum = 0.0f; g_box_sum = 0.0f; g_arrive = 0u; }
        if (tid < 128) { g_bins[tid] = 0.0f; g_cnt[tid] = 0; }
    }
}

// ---------------------------------------------------------------------------
// Launch
// ---------------------------------------------------------------------------
extern "C" void kernel_launch(void* const* d_in, const int* in_sizes, int n_in,
                              void* d_out, int out_size) {
    const float* class_logit       = (const float*)d_in[0];
    const float* box_regression    = (const float*)d_in[1];
    const float* regression_target = (const float*)d_in[2];
    const float* mask_logit        = (const float*)d_in[3];
    const float* proposal          = (const float*)d_in[4];
    const float* gt_mask           = (const float*)d_in[5];
    const int*   matched_idx       = (const int*)d_in[6];
    const int*   label             = (const int*)d_in[7];
    float* out = (float*)d_out;

    int R = in_sizes[4] / 4;                         // proposal [R,4]
    int C = in_sizes[0] / R;                         // class_logit [R,C]
    int num_pos = in_sizes[2] / 4;                   // regression_target [P,4]
    long long mm = (long long)in_sizes[3] / ((long long)R * C);
    int Mo = (int)(sqrtf((float)mm) + 0.5f);         // mask_logit [R,C,Mo,Mo]
    int G = out_size - 2;                            // per_gt bins
    long long hw = (long long)in_sizes[5] / G;       // gt_mask [G,H,W]
    int Hh = (int)(sqrtf((float)hw) + 0.5f);
    int Ww = Hh;

    if (Mo == 28) {
        fused_kernel<28><<<R, 256>>>(class_logit, box_regression, regression_target,
                                     mask_logit, proposal, gt_mask,
                                     matched_idx, label, out,
                                     C, Hh, Ww, Mo, num_pos, R, G);
    } else {
        fused_kernel<0><<<R, 256>>>(class_logit, box_regression, regression_target,
                                    mask_logit, proposal, gt_mask,
                                    matched_idx, label, out,
                                    C, Hh, Ww, Mo, num_pos, R, G);
    }
}

// round 14
// speedup vs baseline: 1.5517x; 1.5517x over previous
#include <cuda_runtime.h>
#include <cuda_bf16.h>
#include <math.h>

// Global accumulators (zero at module load; last block resets each run).
__device__ float        g_bins[128];
__device__ float        g_cls_sum;
__device__ float        g_box_sum;
__device__ unsigned int g_arrive;

// ---------------------------------------------------------------------------
// Single fused kernel: one block (256 thr) per RoI r.  (R8 structure)
//   warps 0-6: mask BCE, one grid row per (warp,iter), lane = column,
//              all 20 loads issued before any consume. WSHIFT>0 makes all
//              feature-map addressing compile-time shifts (Ww=Hh=1<<WSHIFT).
//   warp 7:    cls CE (+ box smooth-L1 if r < num_pos)
//   epilogue:  block reduce, tid0: bins atomic + single release-arrive.
//   LAST block: smem histogram for counts, __ldcg reads, writes 102 outputs,
//              resets globals for the next graph replay.
// ---------------------------------------------------------------------------
template<int MO, int WSHIFT>
__global__ void __launch_bounds__(256, 5) fused_kernel(
        const float* __restrict__ class_logit,
        const float* __restrict__ box_regression,
        const float* __restrict__ regression_target,
        const float* __restrict__ mask_logit,
        const float* __restrict__ proposal,
        const float* __restrict__ gt_mask,
        const int* __restrict__ matched_idx,
        const int* __restrict__ label,
        float* __restrict__ out,
        int C, int Hh_rt, int Ww_rt, int Mo_rt, int num_pos, int R, int G) {
    const int Mo = (MO > 0) ? MO : Mo_rt;
    const int P  = Mo * Mo;
    const int Hh = (WSHIFT > 0) ? (1 << WSHIFT) : Hh_rt;
    const int Ww = (WSHIFT > 0) ? (1 << WSHIFT) : Ww_rt;
    int r    = blockIdx.x;
    int tid  = threadIdx.x;
    int lane = tid & 31;
    int w    = tid >> 5;
    __shared__ float sh[8];
    __shared__ bool  s_last;
    __shared__ int   s_cnt[128];

    int lab = __ldg(&label[r]);
    int b   = __ldg(&matched_idx[r]);

    if (w == 7) {
        // ---- classification CE for this row ----
        const float* row = class_logit + r * C;
        float e0 = (lane      < C) ? __ldg(row + lane)      : -INFINITY;
        float e1 = (lane + 32 < C) ? __ldg(row + lane + 32) : -INFINITY;
        float e2 = (lane + 64 < C) ? __ldg(row + lane + 64) : -INFINITY;
        float mx = fmaxf(e0, fmaxf(e1, e2));
        #pragma unroll
        for (int o = 16; o; o >>= 1) mx = fmaxf(mx, __shfl_xor_sync(0xFFFFFFFFu, mx, o));
        float s2 = 0.0f;
        if (lane      < C) s2 += __expf(e0 - mx);
        if (lane + 32 < C) s2 += __expf(e1 - mx);
        if (lane + 64 < C) s2 += __expf(e2 - mx);
        #pragma unroll
        for (int o = 16; o; o >>= 1) s2 += __shfl_xor_sync(0xFFFFFFFFu, s2, o);
        if (lane == 0) atomicAdd(&g_cls_sum, mx + __logf(s2) - __ldg(row + lab));

        // ---- box smooth-L1 for this row (if positive) ----
        if (r < num_pos) {
            float term = 0.0f;
            if (lane < 4) {
                float pred = __ldg(&box_regression[r * (C * 4) + lab * 4 + lane]);
                float tgt  = __ldg(&regression_target[r * 4 + lane]);
                float d = fabsf(pred - tgt);
                term = (d < 1.0f) ? 0.5f * d * d : d - 0.5f;
            }
            #pragma unroll
            for (int o = 2; o; o >>= 1) term += __shfl_xor_sync(0xFFFFFFFFu, term, o);
            if (lane == 0) atomicAdd(&g_box_sum, term);
        }
        if (lane == 0) sh[7] = 0.0f;
    } else {
        // ---- mask BCE ----
        float acc = 0.0f;
        float4 box = *(const float4*)(proposal + r * 4);
        float x1 = box.x, y1 = box.y, x2 = box.z, y2 = box.w;
        float invMo = 1.0f / (float)Mo;
        float sx = (x2 - x1) * invMo;
        float sy = (y2 - y1) * invMo;
        const float* sel = mask_logit + (r * C + lab) * P;   // <2^31 elements
        const float* fm  = gt_mask + b * (Hh * Ww);          // <2^31 elements

        float prod = 1.0f;

        if (MO == 28) {
            const int ix = lane;                 // lanes 0..27 active
            const bool active = ix < 28;

            // x geometry is row-invariant
            float x  = fmaf((float)ix + 0.5f, sx, x1);
            bool  vx = (x > -1.0f) & (x < (float)Ww);
            float xc = fminf(fmaxf(x, 0.0f), (float)(Ww - 1));
            int   x0 = (int)xc;
            int   xi = min(x0 + 1, Ww - 1);
            float lx = xc - (float)x0;

            // phase 1: geometry for all 4 rows (int32, shift addressing)
            float ly[4]; bool vrow[4];
            int o0[4], o1[4];
            #pragma unroll
            for (int i = 0; i < 4; i++) {
                int row = (w << 2) + i;
                float y = fmaf((float)row + 0.5f, sy, y1);
                vrow[i] = active & vx & (y > -1.0f) & (y < (float)Hh);
                float yc = fminf(fmaxf(y, 0.0f), (float)(Hh - 1));
                int y0 = (int)yc;
                int yi = min(y0 + 1, Hh - 1);
                ly[i] = yc - (float)y0;
                if (WSHIFT > 0) { o0[i] = y0 << WSHIFT; o1[i] = yi << WSHIFT; }
                else            { o0[i] = y0 * Ww;      o1[i] = yi * Ww;      }
            }
            // phase 2: issue ALL loads before any consume
            float v00[4], v01[4], v10[4], v11[4], sl[4];
            #pragma unroll
            for (int i = 0; i < 4; i++) {
                v00[i] = __ldg(fm + o0[i] + x0);
                v01[i] = __ldg(fm + o0[i] + xi);
                v10[i] = __ldg(fm + o1[i] + x0);
                v11[i] = __ldg(fm + o1[i] + xi);
            }
            #pragma unroll
            for (int i = 0; i < 4; i++) {
                int row = (w << 2) + i;
                sl[i] = active ? __ldg(sel + row * 28 + ix) : 0.0f;
            }
            // phase 3: consume
            #pragma unroll
            for (int i = 0; i < 4; i++) {
                float top = fmaf(lx, v01[i] - v00[i], v00[i]);
                float bot = fmaf(lx, v11[i] - v10[i], v10[i]);
                float t = fmaf(ly[i], bot - top, top);
                t = vrow[i] ? t : 0.0f;
                float s = sl[i];
                acc += fmaxf(s, 0.0f) - s * t;
                float f = 1.0f + __expf(-fabsf(s));
                prod *= active ? f : 1.0f;
            }
        } else {
            for (int p = tid; p < P; p += 224) {
                int iy = p / Mo;
                int ix = p - iy * Mo;
                float x = fmaf((float)ix + 0.5f, sx, x1);
                float y = fmaf((float)iy + 0.5f, sy, y1);
                bool valid = (x > -1.0f) & (x < (float)Ww) & (y > -1.0f) & (y < (float)Hh);
                float xc = fminf(fmaxf(x, 0.0f), (float)(Ww - 1));
                float yc = fminf(fmaxf(y, 0.0f), (float)(Hh - 1));
                int x0 = (int)xc, y0 = (int)yc;
                int xi = min(x0 + 1, Ww - 1);
                int yi = min(y0 + 1, Hh - 1);
                float lx = xc - (float)x0, ly = yc - (float)y0;
                const float* r0 = fm + y0 * Ww;
                const float* r1 = fm + yi * Ww;
                float v00 = __ldg(r0 + x0), v01 = __ldg(r0 + xi);
                float v10 = __ldg(r1 + x0), v11 = __ldg(r1 + xi);
                float top = fmaf(lx, v01 - v00, v00);
                float bot = fmaf(lx, v11 - v10, v10);
                float t = fmaf(ly, bot - top, top);
                t = valid ? t : 0.0f;
                float s = __ldg(sel + p);
                acc  += fmaxf(s, 0.0f) - s * t;
                prod *= 1.0f + __expf(-fabsf(s));
            }
        }

        // product across 8-lane groups (factors in (1,2], 4 pts/thread)
        #pragma unroll
        for (int o = 1; o < 8; o <<= 1) prod *= __shfl_xor_sync(0xFFFFFFFFu, prod, o);
        if ((lane & 7) == 0) acc += __logf(prod);

        #pragma unroll
        for (int o = 16; o; o >>= 1) acc += __shfl_xor_sync(0xFFFFFFFFu, acc, o);
        if (lane == 0) sh[w] = acc;
    }
    __syncthreads();   // orders warp7 atomics + sh[] before tid0's arrive

    if (w == 0) {
        float v = (lane < 8) ? sh[lane] : 0.0f;
        #pragma unroll
        for (int o = 4; o; o >>= 1) v += __shfl_xor_sync(0xFFFFFFFFu, v, o);
        if (lane == 0) {
            atomicAdd(&g_bins[b], v / (float)P);
            unsigned int n;
            asm volatile("atom.release.gpu.global.add.u32 %0, [%1], 1;"
                         : "=r"(n) : "l"(&g_arrive) : "memory");
            s_last = (n == (unsigned int)(gridDim.x - 1));
        }
    }
    __syncthreads();

    if (s_last) {
        // per-gt counts: smem histogram of matched_idx (no per-block atomics)
        if (tid < 128) s_cnt[tid] = 0;
        __syncthreads();
        for (int i = tid; i < R; i += 256)
            atomicAdd(&s_cnt[__ldg(&matched_idx[i])], 1);
        __syncthreads();
        // Accumulators are L2-resident atomic results; __ldcg reads L2 directly.
        if (tid == 0) out[0] = __ldcg(&g_cls_sum) / (float)R;
        if (tid == 1) out[1] = __ldcg(&g_box_sum) / (float)R;
        if (tid < G) {
            int c = s_cnt[tid];
            float bsum = __ldcg(&g_bins[tid]);
            out[2 + tid] = (c > 0) ? bsum / (float)c : 0.0f;
        }
        __syncthreads();
        // reset for next graph replay
        if (tid == 0) { g_cls_sum = 0.0f; g_box_sum = 0.0f; g_arrive = 0u; }
        if (tid < 128) g_bins[tid] = 0.0f;
    }
}

// ---------------------------------------------------------------------------
// Launch
// ---------------------------------------------------------------------------
extern "C" void kernel_launch(void* const* d_in, const int* in_sizes, int n_in,
                              void* d_out, int out_size) {
    const float* class_logit       = (const float*)d_in[0];
    const float* box_regression    = (const float*)d_in[1];
    const float* regression_target = (const float*)d_in[2];
    const float* mask_logit        = (const float*)d_in[3];
    const float* proposal          = (const float*)d_in[4];
    const float* gt_mask           = (const float*)d_in[5];
    const int*   matched_idx       = (const int*)d_in[6];
    const int*   label             = (const int*)d_in[7];
    float* out = (float*)d_out;

    int R = in_sizes[4] / 4;                         // proposal [R,4]
    int C = in_sizes[0] / R;                         // class_logit [R,C]
    int num_pos = in_sizes[2] / 4;                   // regression_target [P,4]
    long long mm = (long long)in_sizes[3] / ((long long)R * C);
    int Mo = (int)(sqrtf((float)mm) + 0.5f);         // mask_logit [R,C,Mo,Mo]
    int G = out_size - 2;                            // per_gt bins
    long long hw = (long long)in_sizes[5] / G;       // gt_mask [G,H,W]
    int Hh = (int)(sqrtf((float)hw) + 0.5f);
    int Ww = Hh;

    if (Mo == 28 && Ww == 512 && Hh == 512) {
        fused_kernel<28, 9><<<R, 256>>>(class_logit, box_regression, regression_target,
                                        mask_logit, proposal, gt_mask,
                                        matched_idx, label, out,
                                        C, Hh, Ww, Mo, num_pos, R, G);
    } else if (Mo == 28) {
        fused_kernel<28, 0><<<R, 256>>>(class_logit, box_regression, regression_target,
                                        mask_logit, proposal, gt_mask,
                                        matched_idx, label, out,
                                        C, Hh, Ww, Mo, num_pos, R, G);
    } else {
        fused_kernel<0, 0><<<R, 256>>>(class_logit, box_regression, regression_target,
                                       mask_logit, proposal, gt_mask,
                                       matched_idx, label, out,
                                       C, Hh, Ww, Mo, num_pos, R, G);
    }
}